// round 3
// baseline (speedup 1.0000x reference)
#include <cuda_runtime.h>

// Problem constants (hard-coded by the reference)
#define B_  128
#define C1_ 128
#define C2_ 14
#define S_  14
#define K_  3
#define H_  256
#define E_  2

#define SP_ 16   // padded row length for t4 scratch (14 -> 16 floats)

typedef unsigned long long u64;

// Scratch t4 in OUTPUT layout [b][h][n][SP_] (rows padded to 16 floats so the
// epilogue can use aligned LDG.128). 29.4 MB.
__device__ float g_t4[(size_t)B_ * H_ * C2_ * SP_];

// Packed dual-fp32 FMA (single FFMA2 if ptxas can pair registers)
__device__ __forceinline__ u64 ffma2(u64 a, u64 b, u64 c) {
    u64 d;
    asm("fma.rn.f32x2 %0, %1, %2, %3;" : "=l"(d) : "l"(a), "l"(b), "l"(c));
    return d;
}

__device__ __forceinline__ u64 dupf(float v) {
    unsigned u = __float_as_uint(v);
    return (u64)u | ((u64)u << 32);
}

// ---------------------------------------------------------------------------
// Kernel 1: t4[b,n,m,h] = sum_{j<128, i<3} xpad[b,j,n,m+i] * w1[j,i,h]
// Block = (n-pair, b). 256 threads: nn = tid/128 selects n within the pair,
// hp = tid%128 selects an h-PAIR. 14 packed f32x2 accumulators per thread.
// x window in smem pre-duplicated as (x,x) u64 pairs -> operand packs free.
// NO j-unroll: keeps live regs ~76 so FFMA2 register pairs stay allocatable.
// ---------------------------------------------------------------------------
__global__ __launch_bounds__(256) void conv_t4_kernel(
    const float* __restrict__ x,   // (B, C1*C2, S)
    const float* __restrict__ w1)  // (C1, K, H)
{
    const int n0 = blockIdx.x * 2;
    const int b  = blockIdx.y;

    __shared__ u64 xs[2][C1_][16];

    const int tid = threadIdx.x;

    // Zero pad columns p=0, p=15
    for (int idx = tid; idx < 2 * C1_ * 2; idx += 256) {
        int nn = idx >> 8;
        int r  = idx & 255;
        xs[nn][r >> 1][(r & 1) ? 15 : 0] = 0ull;
    }
    // Interior: xs[nn][j][m+1] = dup(x[b, j*C2 + (n0+nn), m])
    const float* xb = x + (size_t)b * (C1_ * C2_ * S_);
    for (int idx = tid; idx < 2 * C1_ * S_; idx += 256) {
        int nn = idx / (C1_ * S_);
        int r  = idx - nn * (C1_ * S_);
        int j  = r / S_;
        int m  = r - j * S_;
        xs[nn][j][m + 1] = dupf(xb[(j * C2_ + n0 + nn) * S_ + m]);
    }
    __syncthreads();

    const int nn = tid >> 7;
    const int hp = tid & 127;

    u64 acc[S_];
#pragma unroll
    for (int m = 0; m < S_; ++m) acc[m] = 0ull;

    const u64* wp = reinterpret_cast<const u64*>(w1) + hp;  // (h0,h1) pair

    for (int j = 0; j < C1_; ++j) {
        u64 w0v = __ldg(wp + (size_t)(j * K_ + 0) * (H_ / 2));
        u64 w1v = __ldg(wp + (size_t)(j * K_ + 1) * (H_ / 2));
        u64 w2v = __ldg(wp + (size_t)(j * K_ + 2) * (H_ / 2));
        u64 xd[16];
#pragma unroll
        for (int p = 0; p < 16; ++p) xd[p] = xs[nn][j][p];
#pragma unroll
        for (int m = 0; m < S_; ++m) acc[m] = ffma2(xd[m],     w0v, acc[m]);
#pragma unroll
        for (int m = 0; m < S_; ++m) acc[m] = ffma2(xd[m + 1], w1v, acc[m]);
#pragma unroll
        for (int m = 0; m < S_; ++m) acc[m] = ffma2(xd[m + 2], w2v, acc[m]);
    }

    // Store two padded rows: [b][h0][n][0..13] and [b][h1][n][0..13]
    const int n = n0 + nn;
    float lo[S_], hi[S_];
#pragma unroll
    for (int m = 0; m < S_; ++m) {
        lo[m] = __uint_as_float((unsigned)(acc[m]));
        hi[m] = __uint_as_float((unsigned)(acc[m] >> 32));
    }
    float* o0 = g_t4 + (((size_t)b * H_ + 2 * hp)     * C2_ + n) * SP_;
    float* o1 = g_t4 + (((size_t)b * H_ + 2 * hp + 1) * C2_ + n) * SP_;
#pragma unroll
    for (int mm = 0; mm < 7; ++mm) {
        reinterpret_cast<float2*>(o0)[mm] = make_float2(lo[2 * mm], lo[2 * mm + 1]);
        reinterpret_cast<float2*>(o1)[mm] = make_float2(hi[2 * mm], hi[2 * mm + 1]);
    }
}

// ---------------------------------------------------------------------------
// Kernel 2: epilogue, one thread per (b,h,n) output row.
//   out[b,h,n,m] = t4[b,h,n2a,m]*w0[h,e1a] + t4[b,h,n2b,m]*w0[h,e1b]
// Source rows read as 4 aligned LDG.128 each (t4 rows padded to 16 floats;
// the last float4's .z/.w lanes are pad garbage and are discarded).
// ---------------------------------------------------------------------------
__global__ __launch_bounds__(256) void epilogue_kernel(
    const float* __restrict__ w0,       // (H, E)
    const int*   __restrict__ shift_p,  // may be null -> shift = 1
    float*       __restrict__ out)      // (B, H, C2, S)
{
    const int total = B_ * H_ * C2_;
    int idx = blockIdx.x * blockDim.x + threadIdx.x;
    if (idx >= total) return;

    const int n = idx % C2_;
    const int h = (idx / C2_) % H_;

    const int s   = shift_p ? shift_p[0] : 1;
    const int s28 = ((s % 28) + 28) % 28;
    const int s14 = ((s % 14) + 14) % 14;

    int n2[E_];
    float wv[E_];
    const float2 w0p = __ldg(reinterpret_cast<const float2*>(w0) + h);
#pragma unroll
    for (int e = 0; e < E_; ++e) {
        int g  = (n * E_ + e - s28 + 56) % 28;  // merged-axis roll (size 28)
        int n1 = g >> 1;
        int e1 = g & 1;
        n2[e] = (n1 - s14 + 14) % 14;           // C2-axis roll (size 14)
        wv[e] = e1 ? w0p.y : w0p.x;
    }

    const float* plane = g_t4 + (size_t)(idx / C2_) * (C2_ * SP_);
    const float4* pa = reinterpret_cast<const float4*>(plane + n2[0] * SP_);
    const float4* pb = reinterpret_cast<const float4*>(plane + n2[1] * SP_);

    float4 a0 = __ldg(pa + 0), a1 = __ldg(pa + 1), a2 = __ldg(pa + 2), a3 = __ldg(pa + 3);
    float4 b0 = __ldg(pb + 0), b1 = __ldg(pb + 1), b2 = __ldg(pb + 2), b3 = __ldg(pb + 3);

    float r[S_];
    r[0]  = a0.x * wv[0] + b0.x * wv[1];
    r[1]  = a0.y * wv[0] + b0.y * wv[1];
    r[2]  = a0.z * wv[0] + b0.z * wv[1];
    r[3]  = a0.w * wv[0] + b0.w * wv[1];
    r[4]  = a1.x * wv[0] + b1.x * wv[1];
    r[5]  = a1.y * wv[0] + b1.y * wv[1];
    r[6]  = a1.z * wv[0] + b1.z * wv[1];
    r[7]  = a1.w * wv[0] + b1.w * wv[1];
    r[8]  = a2.x * wv[0] + b2.x * wv[1];
    r[9]  = a2.y * wv[0] + b2.y * wv[1];
    r[10] = a2.z * wv[0] + b2.z * wv[1];
    r[11] = a2.w * wv[0] + b2.w * wv[1];
    r[12] = a3.x * wv[0] + b3.x * wv[1];
    r[13] = a3.y * wv[0] + b3.y * wv[1];

    float2* o = reinterpret_cast<float2*>(out + (size_t)idx * S_);
#pragma unroll
    for (int mm = 0; mm < 7; ++mm)
        o[mm] = make_float2(r[2 * mm], r[2 * mm + 1]);
}

// ---------------------------------------------------------------------------
extern "C" void kernel_launch(void* const* d_in, const int* in_sizes, int n_in,
                              void* d_out, int out_size)
{
    const float* x     = (const float*)d_in[0];
    const float* w0    = (const float*)d_in[1];
    const float* w1    = (const float*)d_in[2];
    const int*   shift = (n_in >= 4) ? (const int*)d_in[3] : nullptr;

    (void)in_sizes; (void)out_size;

    dim3 grid1(C2_ / 2, B_);
    conv_t4_kernel<<<grid1, 256>>>(x, w1);

    const int total = B_ * H_ * C2_;
    epilogue_kernel<<<(total + 255) / 256, 256>>>(w0, shift, (float*)d_out);
}

// round 4
// speedup vs baseline: 1.8518x; 1.8518x over previous
#include <cuda_runtime.h>
#include <cstdint>

// Problem constants
#define B_  128
#define C1_ 128
#define C2_ 14
#define S_  14
#define K_  3
#define H_  256

#define THREADS 224   // 7 warps
#define NWARP   7

// Shared-memory word (float) offsets
//  xs: [128 j][14 n][17]  (slot 0 and 15 are zero pad; stride 17 for banks)
//  Bs: 2 x [64 n][36]     (k32 chunk, row stride 36 -> CF fragment reads)
//  Cs: [224 r][68]
#define XS_W   0
#define XS_SZ  (128 * 14 * 17)          // 30464
#define BS_W   XS_SZ
#define BS_STRIDE 36
#define BS_BUF (64 * BS_STRIDE)          // 2304
#define CS_W   (BS_W + 2 * BS_BUF)       // 35072
#define CS_STRIDE 68
#define SMEM_WORDS (CS_W + 224 * CS_STRIDE)   // 50304 words = 201216 B

__device__ __forceinline__ float tf32r(float v) {
    float r;
    asm("cvt.rna.tf32.f32 %0, %1;" : "=f"(r) : "f"(v));
    return r;
}

__device__ __forceinline__ void mma_tf32(float c[4],
                                         unsigned a0, unsigned a1, unsigned a2, unsigned a3,
                                         unsigned b0, unsigned b1) {
    asm volatile(
        "mma.sync.aligned.m16n8k8.row.col.f32.tf32.tf32.f32 "
        "{%0,%1,%2,%3}, {%4,%5,%6,%7}, {%8,%9}, {%0,%1,%2,%3};"
        : "+f"(c[0]), "+f"(c[1]), "+f"(c[2]), "+f"(c[3])
        : "r"(a0), "r"(a1), "r"(a2), "r"(a3), "r"(b0), "r"(b1));
}

// ---------------------------------------------------------------------------
// Fused kernel: per block (b, hh): GEMM tile M=224 ((m,n) rows, m-major),
// N=64 (h chunk), K=384 (i*128+j), tf32 tensor cores; then in-block roll
// epilogue from the C tile in smem, writing final out directly.
// ---------------------------------------------------------------------------
__global__ void __launch_bounds__(THREADS, 1) fused_kernel(
    const float* __restrict__ x,       // (B, C1*C2, S)
    const float* __restrict__ w0,      // (H, E=2)
    const float* __restrict__ w1,      // (C1, K, H)
    const int*   __restrict__ shift_p, // scalar (may be null -> 1)
    float*       __restrict__ out)     // (B, H, C2, S)
{
    extern __shared__ float sm[];

    const int bid = blockIdx.x;
    const int b   = bid >> 2;
    const int hh  = bid & 3;
    const int h0  = hh * 64;

    const int tid  = threadIdx.x;
    const int w    = tid >> 5;
    const int lane = tid & 31;
    const int t    = lane & 3;   // threadID_in_group
    const int q    = lane >> 2;  // groupID

    // ---- Stage x[b] into xs (tf32-rounded), zero pads ----
    const float* xb = x + (size_t)b * (C1_ * C2_ * S_);
    for (int idx4 = tid; idx4 < (C1_ * C2_ * S_) / 4; idx4 += THREADS) {
        float4 v = __ldg(reinterpret_cast<const float4*>(xb) + idx4);
        int j  = idx4 / 49;            // 49 float4 per j (196 floats)
        int rr = (idx4 - j * 49) * 4;  // element index within j
        float vv[4] = {v.x, v.y, v.z, v.w};
#pragma unroll
        for (int l = 0; l < 4; ++l) {
            int e = rr + l;
            int n = e / 14;
            int m = e - n * 14;
            sm[XS_W + j * 238 + n * 17 + m + 1] = tf32r(vv[l]);
        }
    }
    for (int p = tid; p < C1_ * C2_; p += THREADS) {
        int j = p / 14, n = p - (p / 14) * 14;
        sm[XS_W + j * 238 + n * 17 + 0]  = 0.0f;
        sm[XS_W + j * 238 + n * 17 + 15] = 0.0f;
    }

    // ---- Per-thread A-row offsets (rows r = 32w + q + 8u), clamp pad rows ----
    int rw[4];
#pragma unroll
    for (int u = 0; u < 4; ++u) {
        int r  = 32 * w + q + 8 * u;
        int mr = r / 14;
        int nr = r - mr * 14;
        if (mr > 13) mr = 13;          // pad rows read valid garbage
        rw[u] = nr * 17 + mr;
    }

    // ---- B chunk prefetch helpers (k32 chunks; 2048 elements each) ----
    float pv[10];
    auto ldg_b = [&](int c) {
        int i = c >> 2, jb = (c & 3) * 32;
#pragma unroll
        for (int k = 0; k < 10; ++k) {
            int idx = tid + k * THREADS;
            if (idx < 2048) {
                int kk = idx >> 6, nl = idx & 63;
                pv[k] = tf32r(__ldg(w1 + (size_t)((jb + kk) * 3 + i) * H_ + h0 + nl));
            }
        }
    };
    auto sts_b = [&](int buf) {
#pragma unroll
        for (int k = 0; k < 10; ++k) {
            int idx = tid + k * THREADS;
            if (idx < 2048) {
                int kk = idx >> 6, nl = idx & 63;
                sm[BS_W + buf * BS_BUF + nl * BS_STRIDE + kk] = pv[k];
            }
        }
    };

    ldg_b(0);
    sts_b(0);
    __syncthreads();

    // ---- C accumulators: warp tile m32 x n64 = 16 frags ----
    float cf[16][4];
#pragma unroll
    for (int f = 0; f < 16; ++f)
#pragma unroll
        for (int r = 0; r < 4; ++r) cf[f][r] = 0.0f;

    // ---- Main K loop: 12 chunks of k32 ----
    for (int c = 0; c < 12; ++c) {
        if (c < 11) ldg_b(c + 1);

        const int i  = c >> 2;
        const int jb = (c & 3) * 32;
        const int bufw = BS_W + (c & 1) * BS_BUF;

#pragma unroll
        for (int step = 0; step < 4; ++step) {
            const int jc = jb + 8 * step + t;
            const int ab0 = XS_W + jc * 238 + i;
            const int ab4 = ab0 + 4 * 238;

            unsigned a[2][4];
#pragma unroll
            for (int fm = 0; fm < 2; ++fm) {
                a[fm][0] = __float_as_uint(sm[ab0 + rw[2 * fm]]);
                a[fm][1] = __float_as_uint(sm[ab0 + rw[2 * fm + 1]]);
                a[fm][2] = __float_as_uint(sm[ab4 + rw[2 * fm]]);
                a[fm][3] = __float_as_uint(sm[ab4 + rw[2 * fm + 1]]);
            }
            const int brow = 8 * step + t;
#pragma unroll
            for (int fn = 0; fn < 8; ++fn) {
                unsigned b0 = __float_as_uint(sm[bufw + (8 * fn + q) * BS_STRIDE + brow]);
                unsigned b1 = __float_as_uint(sm[bufw + (8 * fn + q) * BS_STRIDE + brow + 4]);
                mma_tf32(cf[0 * 8 + fn], a[0][0], a[0][1], a[0][2], a[0][3], b0, b1);
                mma_tf32(cf[1 * 8 + fn], a[1][0], a[1][1], a[1][2], a[1][3], b0, b1);
            }
        }

        if (c < 11) sts_b((c + 1) & 1);
        __syncthreads();
    }

    // ---- Write C tile to smem Cs ----
#pragma unroll
    for (int fm = 0; fm < 2; ++fm) {
#pragma unroll
        for (int fn = 0; fn < 8; ++fn) {
            const float* cc = cf[fm * 8 + fn];
            int r1  = 32 * w + 16 * fm + q;
            int r2  = r1 + 8;
            int col = 8 * fn + 2 * t;
            *reinterpret_cast<float2*>(&sm[CS_W + r1 * CS_STRIDE + col]) = make_float2(cc[0], cc[1]);
            *reinterpret_cast<float2*>(&sm[CS_W + r2 * CS_STRIDE + col]) = make_float2(cc[2], cc[3]);
        }
    }
    __syncthreads();

    // ---- Fused roll epilogue: out[b,h,n,m] from Cs rows (m*14 + n2) ----
    const int s   = shift_p ? shift_p[0] : 1;
    const int s28 = ((s % 28) + 28) % 28;
    const int s14 = ((s % 14) + 14) % 14;

#pragma unroll
    for (int it = 0; it < 4; ++it) {
        int idx = it * THREADS + tid;   // 0..895
        int h_l = idx & 63;
        int nb  = idx >> 6;             // 0..13

        float2 w0p = __ldg(reinterpret_cast<const float2*>(w0) + (h0 + h_l));

        int n2[2];
        float wv[2];
#pragma unroll
        for (int e = 0; e < 2; ++e) {
            int g  = (nb * 2 + e - s28 + 56) % 28;
            int n1 = g >> 1;
            int e1 = g & 1;
            n2[e]  = (n1 - s14 + 14) % 14;
            wv[e]  = e1 ? w0p.y : w0p.x;
        }

        float* orow = out + (size_t)(b * H_ + h0 + h_l) * (C2_ * S_) + nb * S_;
#pragma unroll
        for (int mm = 0; mm < 7; ++mm) {
            int m0 = 2 * mm, m1 = 2 * mm + 1;
            float v0 = sm[CS_W + (m0 * 14 + n2[0]) * CS_STRIDE + h_l] * wv[0]
                     + sm[CS_W + (m0 * 14 + n2[1]) * CS_STRIDE + h_l] * wv[1];
            float v1 = sm[CS_W + (m1 * 14 + n2[0]) * CS_STRIDE + h_l] * wv[0]
                     + sm[CS_W + (m1 * 14 + n2[1]) * CS_STRIDE + h_l] * wv[1];
            *reinterpret_cast<float2*>(orow + m0) = make_float2(v0, v1);
        }
    }
}

// ---------------------------------------------------------------------------
extern "C" void kernel_launch(void* const* d_in, const int* in_sizes, int n_in,
                              void* d_out, int out_size)
{
    const float* x     = (const float*)d_in[0];
    const float* w0    = (const float*)d_in[1];
    const float* w1    = (const float*)d_in[2];
    const int*   shift = (n_in >= 4) ? (const int*)d_in[3] : nullptr;

    (void)in_sizes; (void)out_size;

    cudaFuncSetAttribute(fused_kernel,
                         cudaFuncAttributeMaxDynamicSharedMemorySize,
                         SMEM_WORDS * 4);

    fused_kernel<<<B_ * 4, THREADS, SMEM_WORDS * 4>>>(x, w0, w1, shift, (float*)d_out);
}

// round 5
// speedup vs baseline: 1.9818x; 1.0702x over previous
#include <cuda_runtime.h>
#include <cstdint>

// Problem constants
#define B_  128
#define C1_ 128
#define C2_ 14
#define S_  14
#define H_  256

#define THREADS 224   // 7 warps

// Shared memory word layout (floats):
//  x slices: 2 buffers of [32 j][14 n][17]  (slots 0,15 zero-pad)
//  Bs:       2 buffers of [32 n][36]
//  Cs:       [224 r][36]  -- aliased onto the x-slice region after mainloop
#define XBUF_W  (32 * 14 * 17)            // 7616
#define BS_W    (2 * XBUF_W)              // 15232
#define BS_STRIDE 36
#define BS_BUF  (32 * BS_STRIDE)          // 1152
#define CS_STRIDE 36
#define SMEM_WORDS (BS_W + 2 * BS_BUF)    // 17536 words = 70144 B

__device__ __forceinline__ float tf32r(float v) {
    float r;
    asm("cvt.rna.tf32.f32 %0, %1;" : "=f"(r) : "f"(v));
    return r;
}

__device__ __forceinline__ void mma_tf32(float c[4],
                                         unsigned a0, unsigned a1, unsigned a2, unsigned a3,
                                         unsigned b0, unsigned b1) {
    asm volatile(
        "mma.sync.aligned.m16n8k8.row.col.f32.tf32.tf32.f32 "
        "{%0,%1,%2,%3}, {%4,%5,%6,%7}, {%8,%9}, {%0,%1,%2,%3};"
        : "+f"(c[0]), "+f"(c[1]), "+f"(c[2]), "+f"(c[3])
        : "r"(a0), "r"(a1), "r"(a2), "r"(a3), "r"(b0), "r"(b1));
}

// ---------------------------------------------------------------------------
// Fused kernel. Block = (b, 32-h chunk). GEMM: M=224 rows r=(m*14+n),
// N=32 (h), K=384=(i,j), tf32 MMA. K loop = 4 j-blocks x 3 i-chunks; x slice
// (32 j) double-buffered and reused across the 3 i-chunks. Fused roll
// epilogue from the C tile in smem.
// ---------------------------------------------------------------------------
__global__ void __launch_bounds__(THREADS, 2) fused_kernel(
    const float* __restrict__ x,       // (B, C1*C2, S)
    const float* __restrict__ w0,      // (H, 2)
    const float* __restrict__ w1,      // (C1, 3, H)
    const int*   __restrict__ shift_p, // scalar (may be null -> 1)
    float*       __restrict__ out)     // (B, H, C2, S)
{
    extern __shared__ float sm[];

    const int bid = blockIdx.x;
    const int b   = bid >> 3;
    const int h0  = (bid & 7) * 32;

    const int tid  = threadIdx.x;
    const int w    = tid >> 5;
    const int lane = tid & 31;
    const int t    = lane & 3;
    const int q    = lane >> 2;

    // ---- Zero the static pad slots of BOTH x buffers (never overwritten) ----
    for (int p = tid; p < 2 * 32 * 14; p += THREADS) {
        int buf = p >= 448;
        int r   = p - buf * 448;
        int j   = r / 14, n = r - (r / 14) * 14;
        int base = buf * XBUF_W + j * 238 + n * 17;
        sm[base + 0]  = 0.0f;
        sm[base + 15] = 0.0f;
    }

    const float* xb = x + (size_t)b * (C1_ * C2_ * S_);

    // ---- x-slice staging: 32 j rows (6272 floats = 1568 float4, 7/thread) ----
    float4 xr[7];
    auto ldg_x = [&](int jb) {
#pragma unroll
        for (int k = 0; k < 7; ++k) {
            int idx4 = tid + k * THREADS;           // 0..1567
            int j = idx4 / 49, f = idx4 - j * 49;
            xr[k] = __ldg(reinterpret_cast<const float4*>(xb) + (jb * 32 + j) * 49 + f);
        }
    };
    auto sts_x = [&](int buf) {
#pragma unroll
        for (int k = 0; k < 7; ++k) {
            int idx4 = tid + k * THREADS;
            int j = idx4 / 49, f = idx4 - j * 49;
            int e = f * 4;
            float v[4] = {xr[k].x, xr[k].y, xr[k].z, xr[k].w};
#pragma unroll
            for (int l = 0; l < 4; ++l) {
                int ee = e + l;
                int n = ee / 14, m = ee - n * 14;
                sm[buf * XBUF_W + j * 238 + n * 17 + m + 1] = tf32r(v[l]);
            }
        }
    };

    // ---- B-chunk staging: 32k x 32n = 1024 floats (5/thread) ----
    float pv[5];
    auto ldg_bw = [&](int jb, int i) {
#pragma unroll
        for (int k = 0; k < 5; ++k) {
            int idx = tid + k * THREADS;
            if (idx < 1024) {
                int kk = idx >> 5, nl = idx & 31;
                pv[k] = __ldg(w1 + (size_t)((jb * 32 + kk) * 3 + i) * H_ + h0 + nl);
            }
        }
    };
    auto sts_bw = [&](int buf) {
#pragma unroll
        for (int k = 0; k < 5; ++k) {
            int idx = tid + k * THREADS;
            if (idx < 1024) {
                int kk = idx >> 5, nl = idx & 31;
                sm[BS_W + buf * BS_BUF + nl * BS_STRIDE + kk] = tf32r(pv[k]);
            }
        }
    };

    // ---- Per-thread A-row offsets (r = 32w + q + 8u), clamp pad rows ----
    int rw[4];
#pragma unroll
    for (int u = 0; u < 4; ++u) {
        int r  = 32 * w + q + 8 * u;
        int mr = r / 14;
        int nr = r - mr * 14;
        if (mr > 13) mr = 13;
        rw[u] = nr * 17 + mr;
    }

    // ---- Prologue: stage (jb=0) x slice and (jb=0,i=0) B chunk ----
    ldg_x(0);
    ldg_bw(0, 0);
    sts_x(0);
    sts_bw(0);
    __syncthreads();

    float cf[8][4];   // [fm*4+fn][..], warp tile m32 x n32
#pragma unroll
    for (int f = 0; f < 8; ++f)
#pragma unroll
        for (int r = 0; r < 4; ++r) cf[f][r] = 0.0f;

    // ---- Main K loop: 12 chunks = 4 j-blocks x 3 i ----
    int jb = 0, ii = 0;
#pragma unroll 1
    for (int c = 0; c < 12; ++c) {
        const int xw = (jb & 1) * XBUF_W;
        const int bw = BS_W + (c & 1) * BS_BUF;

        const bool lastc = (c == 11);
        const int  njb = (ii == 2) ? jb + 1 : jb;
        const int  nii = (ii == 2) ? 0 : ii + 1;

        if (!lastc) ldg_bw(njb, nii);
        if (ii == 0 && jb < 3) ldg_x(jb + 1);

#pragma unroll
        for (int step = 0; step < 4; ++step) {
            const int jloc = 8 * step + t;
            const int ab0 = xw + jloc * 238 + ii;
            const int ab4 = ab0 + 4 * 238;

            unsigned a[2][4];
#pragma unroll
            for (int fm = 0; fm < 2; ++fm) {
                a[fm][0] = __float_as_uint(sm[ab0 + rw[2 * fm]]);
                a[fm][1] = __float_as_uint(sm[ab0 + rw[2 * fm + 1]]);
                a[fm][2] = __float_as_uint(sm[ab4 + rw[2 * fm]]);
                a[fm][3] = __float_as_uint(sm[ab4 + rw[2 * fm + 1]]);
            }
            const int brow = 8 * step + t;
#pragma unroll
            for (int fn = 0; fn < 4; ++fn) {
                unsigned b0 = __float_as_uint(sm[bw + (8 * fn + q) * BS_STRIDE + brow]);
                unsigned b1 = __float_as_uint(sm[bw + (8 * fn + q) * BS_STRIDE + brow + 4]);
                mma_tf32(cf[fn],     a[0][0], a[0][1], a[0][2], a[0][3], b0, b1);
                mma_tf32(cf[4 + fn], a[1][0], a[1][1], a[1][2], a[1][3], b0, b1);
            }
        }

        if (ii == 2 && jb < 3) sts_x((jb + 1) & 1);
        if (!lastc) sts_bw((c + 1) & 1);
        __syncthreads();

        jb = njb; ii = nii;
    }

    // ---- Write C tile to smem (aliases the x-slice region) ----
#pragma unroll
    for (int fm = 0; fm < 2; ++fm) {
#pragma unroll
        for (int fn = 0; fn < 4; ++fn) {
            const float* cc = cf[fm * 4 + fn];
            int r1  = 32 * w + 16 * fm + q;
            int r2  = r1 + 8;
            int col = 8 * fn + 2 * t;
            *reinterpret_cast<float2*>(&sm[r1 * CS_STRIDE + col]) = make_float2(cc[0], cc[1]);
            *reinterpret_cast<float2*>(&sm[r2 * CS_STRIDE + col]) = make_float2(cc[2], cc[3]);
        }
    }
    __syncthreads();

    // ---- Fused roll epilogue: out[b, h0+h_l, nb, :] ----
    const int s   = shift_p ? shift_p[0] : 1;
    const int s28 = ((s % 28) + 28) % 28;
    const int s14 = ((s % 14) + 14) % 14;

#pragma unroll
    for (int it = 0; it < 2; ++it) {
        int idx = it * THREADS + tid;   // 0..447
        int h_l = idx & 31;
        int nb  = idx >> 5;             // 0..13

        float2 w0p = __ldg(reinterpret_cast<const float2*>(w0) + (h0 + h_l));

        int n2[2];
        float wv[2];
#pragma unroll
        for (int e = 0; e < 2; ++e) {
            int g  = (nb * 2 + e - s28 + 56) % 28;
            int n1 = g >> 1;
            int e1 = g & 1;
            n2[e]  = (n1 - s14 + 14) % 14;
            wv[e]  = e1 ? w0p.y : w0p.x;
        }

        float* orow = out + (size_t)(b * H_ + h0 + h_l) * (C2_ * S_) + nb * S_;
#pragma unroll
        for (int mm = 0; mm < 7; ++mm) {
            int m0 = 2 * mm, m1 = 2 * mm + 1;
            float v0 = sm[(m0 * 14 + n2[0]) * CS_STRIDE + h_l] * wv[0]
                     + sm[(m0 * 14 + n2[1]) * CS_STRIDE + h_l] * wv[1];
            float v1 = sm[(m1 * 14 + n2[0]) * CS_STRIDE + h_l] * wv[0]
                     + sm[(m1 * 14 + n2[1]) * CS_STRIDE + h_l] * wv[1];
            *reinterpret_cast<float2*>(orow + m0) = make_float2(v0, v1);
        }
    }
}

// ---------------------------------------------------------------------------
extern "C" void kernel_launch(void* const* d_in, const int* in_sizes, int n_in,
                              void* d_out, int out_size)
{
    const float* x     = (const float*)d_in[0];
    const float* w0    = (const float*)d_in[1];
    const float* w1    = (const float*)d_in[2];
    const int*   shift = (n_in >= 4) ? (const int*)d_in[3] : nullptr;

    (void)in_sizes; (void)out_size;

    cudaFuncSetAttribute(fused_kernel,
                         cudaFuncAttributeMaxDynamicSharedMemorySize,
                         SMEM_WORDS * 4);

    fused_kernel<<<B_ * 8, THREADS, SMEM_WORDS * 4>>>(x, w0, w1, shift, (float*)d_out);
}